// round 5
// baseline (speedup 1.0000x reference)
#include <cuda_runtime.h>
#include <cuda_bf16.h>
#include <cstdint>
#include <cstdio>

// ---------------------------------------------------------------------------
// Problem constants
// ---------------------------------------------------------------------------
#define NB 1024
static const int D_TOT = 267696;

static const int H_OFFS[20] = {0,432,2736,5040,7344,9648,11952,14256,18864,28080,
                               37296,46512,55728,64944,83376,120240,157104,193968,230832,267696};

// ---------------------------------------------------------------------------
// Device scratch (no allocations allowed -> __device__ globals)
// ---------------------------------------------------------------------------
#define BUF_ELEMS (1024*16*32*32)
__device__ float  g_bufA[BUF_ELEMS];
__device__ float  g_bufB[BUF_ELEMS];
__device__ float  g_bufC[BUF_ELEMS];
__device__ float  g_w[267696];       // natural per-layer layout: [oc][ic][3][3]
__device__ double g_stats[19*64*2];  // per layer, per channel: sum, sumsq

// ---------------------------------------------------------------------------
// tf32 helpers (legacy mma.sync path -- works on plain sm_103 target)
// ---------------------------------------------------------------------------
__device__ __forceinline__ uint32_t f2tf32(float v) {
    uint32_t u; asm("cvt.rna.tf32.f32 %0, %1;" : "=r"(u) : "f"(v)); return u;
}
__device__ __forceinline__ void mma_tf32(float c[4],
                                         uint32_t a0, uint32_t a1, uint32_t a2, uint32_t a3,
                                         uint32_t b0, uint32_t b1) {
    asm volatile(
        "mma.sync.aligned.m16n8k8.row.col.f32.tf32.tf32.f32 "
        "{%0,%1,%2,%3}, {%4,%5,%6,%7}, {%8,%9}, {%0,%1,%2,%3};"
        : "+f"(c[0]), "+f"(c[1]), "+f"(c[2]), "+f"(c[3])
        : "r"(a0), "r"(a1), "r"(a2), "r"(a3), "r"(b0), "r"(b1));
}

// ---------------------------------------------------------------------------
// Zero the BN stat accumulators (start of every graph replay)
// ---------------------------------------------------------------------------
__global__ void zstats_k(double* __restrict__ st) {
    int i = blockIdx.x * blockDim.x + threadIdx.x;
    if (i < 19*64*2) st[i] = 0.0;
}

// ---------------------------------------------------------------------------
// Reconstruct w_flat = origin + new_param @ P  (natural layout)
// ---------------------------------------------------------------------------
__global__ void wbuild_k(const float* __restrict__ ow, const float* __restrict__ P,
                         const float* __restrict__ npar, float* __restrict__ wt) {
    __shared__ float s_np[40];
    if (threadIdx.x < 40) s_np[threadIdx.x] = npar[threadIdx.x];
    __syncthreads();
    int d = blockIdx.x * blockDim.x + threadIdx.x;
    if (d >= D_TOT) return;
    float a = ow[d];
#pragma unroll
    for (int j = 0; j < 40; j++)
        a = fmaf(s_np[j], P[(size_t)j * D_TOT + d], a);
    wt[d] = a;
}

// ---------------------------------------------------------------------------
// Implicit-GEMM conv via mma.sync m16n8k8 tf32.
//   CTA = 256 threads (8 warps), M tile = 128 output positions.
//   Warp w owns rows [16w, 16w+16); N = COUT via COUT/8 col-fragments;
//   K = CIN*9, chunked by ICC input channels.
//   A (im2col) and B (weights) staged in smem as tf32 bits, row-major,
//   row pitch KPAD = KUSE+4 words (conflict-free fragment loads).
//   Epilogue: frags -> smem [COUT][128] -> coalesced NCHW store + BN stats.
// ---------------------------------------------------------------------------
template<int CIN, int COUT, int HIN, int STRIDE, bool BN_IN>
__global__ void __launch_bounds__(256)
convmma_k(const float* __restrict__ in, const float* __restrict__ wl,
          float* __restrict__ out, const double* __restrict__ st_in,
          double* __restrict__ st_out)
{
    constexpr int HOUT   = HIN / STRIDE;
    constexpr int NPOS   = HOUT * HOUT;
    constexpr int ICC    = (CIN < 16) ? CIN : 16;
    constexpr int NCHUNK = CIN / ICC;
    constexpr int KC     = ICC * 9;
    constexpr int KUSE   = ((KC + 7) / 8) * 8;
    constexpr int KPAD   = KUSE + 4;
    constexpr int NC     = COUT / 8;

    extern __shared__ float smf[];
    float* s_sc = smf;            // [64]
    float* s_sh = smf + 64;       // [64]
    float* s_a  = smf + 128;      // [128][KPAD]
    float* s_b  = s_a + 128 * KPAD; // [COUT][KPAD]

    const int tid = threadIdx.x, wid = tid >> 5, lane = tid & 31;
    const int g = lane >> 2, t = lane & 3;

    if (BN_IN && tid < CIN) {
        const double cnt = 1024.0 * HIN * HIN;
        double mm = st_in[tid*2]   / cnt;
        double vv = st_in[tid*2+1] / cnt - mm * mm;
        float rs = rsqrtf((float)vv + 1e-5f);
        s_sc[tid] = rs;
        s_sh[tid] = (float)(-mm) * rs;
    }
    if (BN_IN) __syncthreads();

    // staging coords: 2 threads per A-row
    const int m    = tid >> 1, half = tid & 1;
    const int gp   = blockIdx.x * 128 + m;
    const int n    = gp / NPOS;
    const int p    = gp - n * NPOS;
    const int oy   = p / HOUT, ox = p - (p / HOUT) * HOUT;
    const float* inb = in + (size_t)n * CIN * HIN * HIN;

    float acc[NC][4];
#pragma unroll
    for (int nc = 0; nc < NC; nc++)
#pragma unroll
        for (int i = 0; i < 4; i++) acc[nc][i] = 0.f;

    for (int ch = 0; ch < NCHUNK; ch++) {
        const int ic0 = ch * ICC;
        __syncthreads();   // previous chunk's reads done before restage

        // ---- stage A (im2col patches, tf32 bits) ----
        constexpr int LH = (ICC + 1) / 2;
        const int lbeg = half * LH;
        const int lend = (lbeg + LH < ICC) ? lbeg + LH : ICC;
        uint32_t* rowp = (uint32_t*)s_a + m * KPAD;
#pragma unroll 1
        for (int li = lbeg; li < lend; li++) {
            const int ic = ic0 + li;
            const float* cb = inb + ic * HIN * HIN;
            float sc = 1.f, sh = 0.f;
            if (BN_IN) { sc = s_sc[ic]; sh = s_sh[ic]; }
            const int c9 = li * 9;
#pragma unroll
            for (int ky = 0; ky < 3; ky++) {
                const int iy = oy * STRIDE + ky - 1;
                const bool yok = (unsigned)iy < (unsigned)HIN;
#pragma unroll
                for (int kx = 0; kx < 3; kx++) {
                    const int ix = ox * STRIDE + kx - 1;
                    float v = 0.f;
                    if (yok && (unsigned)ix < (unsigned)HIN) {
                        v = __ldg(cb + iy * HIN + ix);
                        if (BN_IN) v = fmaxf(fmaf(v, sc, sh), 0.f);
                    }
                    rowp[c9 + ky * 3 + kx] = f2tf32(v);
                }
            }
        }
        if (KUSE > KC && half == 1) {      // zero tail cols (only CIN=3 case)
#pragma unroll
            for (int c = KC; c < KUSE; c++) rowp[c] = 0u;
        }

        // ---- stage B (weights: row per oc) ----
        for (int idx = tid; idx < COUT * KUSE; idx += 256) {
            const int oc = idx / KUSE;
            const int c  = idx - oc * KUSE;
            float v = (c < KC) ? wl[oc * (CIN * 9) + ic0 * 9 + c] : 0.f;
            ((uint32_t*)s_b)[oc * KPAD + c] = f2tf32(v);
        }
        __syncthreads();

        // ---- K loop: KUSE/8 mma steps ----
        const uint32_t* A0 = (const uint32_t*)s_a + (wid * 16 + g) * KPAD;
        const uint32_t* A1 = A0 + 8 * KPAD;
#pragma unroll
        for (int s = 0; s < KUSE / 8; s++) {
            const int k0 = s * 8;
            uint32_t a0 = A0[k0 + t],     a2 = A0[k0 + t + 4];
            uint32_t a1 = A1[k0 + t],     a3 = A1[k0 + t + 4];
#pragma unroll
            for (int nc = 0; nc < NC; nc++) {
                const uint32_t* B0 = (const uint32_t*)s_b + (nc * 8 + g) * KPAD;
                mma_tf32(acc[nc], a0, a1, a2, a3, B0[k0 + t], B0[k0 + t + 4]);
            }
        }
    }

    // ---- epilogue: frags -> smem staging [COUT][128] ----
    __syncthreads();
    float* s_st  = s_a;                 // 128*KPAD >= COUT*128 always
    float* s_red = s_b;                 // [4][COUT][2]
#pragma unroll
    for (int nc = 0; nc < NC; nc++) {
        const int cb = nc * 8 + 2 * t;
        const int r0 = wid * 16 + g;
        s_st[(cb + 0) * 128 + r0]     = acc[nc][0];
        s_st[(cb + 1) * 128 + r0]     = acc[nc][1];
        s_st[(cb + 0) * 128 + r0 + 8] = acc[nc][2];
        s_st[(cb + 1) * 128 + r0 + 8] = acc[nc][3];
    }
    __syncthreads();

    // coalesced NCHW store
    const int blk128 = blockIdx.x * 128;
    for (int idx = tid; idx < COUT * 128; idx += 256) {
        const int c  = idx >> 7;
        const int mm = idx & 127;
        const int g2 = blk128 + mm;
        const int n2 = g2 / NPOS;
        const int p2 = g2 - n2 * NPOS;
        out[(size_t)n2 * COUT * NPOS + (size_t)c * NPOS + p2] = s_st[idx];
    }

    // BN stats: threads 0..127 each own one row
    if (tid < 128) {
#pragma unroll
        for (int c = 0; c < COUT; c++) {
            float v = s_st[c * 128 + tid];
            float s = v, q = v * v;
#pragma unroll
            for (int off = 16; off; off >>= 1) {
                s += __shfl_down_sync(0xffffffffu, s, off);
                q += __shfl_down_sync(0xffffffffu, q, off);
            }
            if (lane == 0) {
                s_red[(wid * COUT + c) * 2 + 0] = s;
                s_red[(wid * COUT + c) * 2 + 1] = q;
            }
        }
    }
    __syncthreads();
    if (tid < COUT) {
        float s = 0.f, q = 0.f;
#pragma unroll
        for (int w4 = 0; w4 < 4; w4++) {
            s += s_red[(w4 * COUT + tid) * 2 + 0];
            q += s_red[(w4 * COUT + tid) * 2 + 1];
        }
        atomicAdd(&st_out[tid * 2 + 0], (double)s);
        atomicAdd(&st_out[tid * 2 + 1], (double)q);
    }
}

// ---------------------------------------------------------------------------
// Residual epilogue: out = relu( bn(h) + shortcut(prev) )
// ---------------------------------------------------------------------------
template<int C, int H, int MODE, int CPREV>
__global__ void __launch_bounds__(256)
elem_k(const float* __restrict__ h, const double* __restrict__ st,
       const float* __restrict__ prev, float* __restrict__ out)
{
    __shared__ float s_sc[C], s_sh[C];
    if (threadIdx.x < C) {
        const double cnt = 1024.0 * H * H;
        double m = st[threadIdx.x*2]   / cnt;
        double v = st[threadIdx.x*2+1] / cnt - m * m;
        float rs = rsqrtf((float)v + 1e-5f);
        s_sc[threadIdx.x] = rs;
        s_sh[threadIdx.x] = (float)(-m) * rs;
    }
    __syncthreads();

    const int total = 1024 * C * H * H;
    for (int idx = blockIdx.x * blockDim.x + threadIdx.x; idx < total;
         idx += gridDim.x * blockDim.x) {
        int hw = idx % (H * H);
        int c  = (idx / (H * H)) % C;
        int n  = idx / (H * H * C);
        float v = fmaf(h[idx], s_sc[c], s_sh[c]);
        float s = 0.f;
        if (MODE == 1) {
            s = prev[idx];
        } else if (MODE == 2) {
            const int pc = c - (C - CPREV) / 2;
            if (pc >= 0 && pc < CPREV) {
                int y = hw / H, x = hw - y * H;
                s = prev[((size_t)n * CPREV + pc) * (4 * H * H) + (2*y) * (2*H) + 2*x];
            }
        }
        out[idx] = fmaxf(v + s, 0.f);
    }
}

// ---------------------------------------------------------------------------
// Global average pool (8x8) + FC 64->10
// ---------------------------------------------------------------------------
__global__ void __launch_bounds__(64)
poolfc_k(const float* __restrict__ in, const float* __restrict__ Wfc,
         const float* __restrict__ bfc, float* __restrict__ out)
{
    __shared__ float pooled[64];
    const int n = blockIdx.x, t = threadIdx.x;
    const float* p = in + (size_t)n * 64 * 64;
    float s = 0.f;
#pragma unroll
    for (int i = 0; i < 64; i++) s += p[t * 64 + i];
    pooled[t] = s * (1.f / 64.f);
    __syncthreads();
    if (t < 10) {
        float a = bfc[t];
#pragma unroll
        for (int c = 0; c < 64; c++) a = fmaf(Wfc[t * 64 + c], pooled[c], a);
        out[n * 10 + t] = a;
    }
}

// ---------------------------------------------------------------------------
// Host-side smem size (mirror of kernel constants)
// ---------------------------------------------------------------------------
static constexpr int cm_smem(int CIN, int COUT) {
    int ICC  = (CIN < 16) ? CIN : 16;
    int KUSE = ((ICC * 9 + 7) / 8) * 8;
    int KPAD = KUSE + 4;
    return (128 + 128 * KPAD + COUT * KPAD) * 4;
}

extern "C" void kernel_launch(void* const* d_in, const int* in_sizes, int n_in,
                              void* d_out, int out_size)
{
    (void)in_sizes; (void)n_in; (void)out_size;
    const float* x   = (const float*)d_in[0];
    const float* ow  = (const float*)d_in[1];
    const float* P   = (const float*)d_in[2];
    const float* npar= (const float*)d_in[3];
    const float* Wfc = (const float*)d_in[4];
    const float* bfc = (const float*)d_in[5];
    float* y = (float*)d_out;

    float *A, *B, *C, *w; double* st;
    cudaGetSymbolAddress((void**)&A, g_bufA);
    cudaGetSymbolAddress((void**)&B, g_bufB);
    cudaGetSymbolAddress((void**)&C, g_bufC);
    cudaGetSymbolAddress((void**)&w, g_w);
    cudaGetSymbolAddress((void**)&st, g_stats);

    cudaFuncSetAttribute(convmma_k< 3,16,32,1,false>, cudaFuncAttributeMaxDynamicSharedMemorySize, cm_smem( 3,16));
    cudaFuncSetAttribute(convmma_k<16,16,32,1,false>, cudaFuncAttributeMaxDynamicSharedMemorySize, cm_smem(16,16));
    cudaFuncSetAttribute(convmma_k<16,16,32,1,true >, cudaFuncAttributeMaxDynamicSharedMemorySize, cm_smem(16,16));
    cudaFuncSetAttribute(convmma_k<16,32,32,2,false>, cudaFuncAttributeMaxDynamicSharedMemorySize, cm_smem(16,32));
    cudaFuncSetAttribute(convmma_k<32,32,16,1,true >, cudaFuncAttributeMaxDynamicSharedMemorySize, cm_smem(32,32));
    cudaFuncSetAttribute(convmma_k<32,32,16,1,false>, cudaFuncAttributeMaxDynamicSharedMemorySize, cm_smem(32,32));
    cudaFuncSetAttribute(convmma_k<32,64,16,2,false>, cudaFuncAttributeMaxDynamicSharedMemorySize, cm_smem(32,64));
    cudaFuncSetAttribute(convmma_k<64,64, 8,1,true >, cudaFuncAttributeMaxDynamicSharedMemorySize, cm_smem(64,64));
    cudaFuncSetAttribute(convmma_k<64,64, 8,1,false>, cudaFuncAttributeMaxDynamicSharedMemorySize, cm_smem(64,64));

    auto ST = [&](int l) { return st + l * 128; };

    zstats_k<<<(19*64*2 + 255)/256, 256>>>(st);
    wbuild_k<<<(D_TOT + 255)/256, 256>>>(ow, P, npar, w);

    // tiles per layer = 1024*NPOS/128
    constexpr int T32 = 8192;   // 32x32 output
    constexpr int T16 = 2048;   // 16x16 output
    constexpr int T8  = 512;    // 8x8 output

    // ---- layer 0 ----
    convmma_k<3,16,32,1,false><<<T32,256,cm_smem(3,16)>>>(x, w + H_OFFS[0], A, nullptr, ST(0));
    elem_k<16,32,0,16><<<4096,256>>>(A, ST(0), nullptr, B);

    float* o  = B;
    float* h  = C;
    float* h2 = A;
#define ROT() { float* t = o; o = h; h = h2; h2 = t; }

    // ---- stage 1: 16ch @32x32 ----
    for (int b = 0; b < 3; b++) {
        int la = 1 + 2*b, lb = la + 1;
        convmma_k<16,16,32,1,false><<<T32,256,cm_smem(16,16)>>>(o, w + H_OFFS[la], h,  nullptr, ST(la));
        convmma_k<16,16,32,1,true ><<<T32,256,cm_smem(16,16)>>>(h, w + H_OFFS[lb], h2, ST(la),  ST(lb));
        elem_k<16,32,1,16><<<4096,256>>>(h2, ST(lb), o, h);
        ROT();
    }

    // ---- block 4: 16->32, stride 2 ----
    convmma_k<16,32,32,2,false><<<T16,256,cm_smem(16,32)>>>(o, w + H_OFFS[7], h,  nullptr, ST(7));
    convmma_k<32,32,16,1,true ><<<T16,256,cm_smem(32,32)>>>(h, w + H_OFFS[8], h2, ST(7),   ST(8));
    elem_k<32,16,2,16><<<4096,256>>>(h2, ST(8), o, h);
    ROT();

    // ---- blocks 5,6: 32ch @16x16 ----
    for (int b = 0; b < 2; b++) {
        int la = 9 + 2*b, lb = la + 1;
        convmma_k<32,32,16,1,false><<<T16,256,cm_smem(32,32)>>>(o, w + H_OFFS[la], h,  nullptr, ST(la));
        convmma_k<32,32,16,1,true ><<<T16,256,cm_smem(32,32)>>>(h, w + H_OFFS[lb], h2, ST(la),  ST(lb));
        elem_k<32,16,1,32><<<4096,256>>>(h2, ST(lb), o, h);
        ROT();
    }

    // ---- block 7: 32->64, stride 2 ----
    convmma_k<32,64,16,2,false><<<T8,256,cm_smem(32,64)>>>(o, w + H_OFFS[13], h,  nullptr, ST(13));
    convmma_k<64,64, 8,1,true ><<<T8,256,cm_smem(64,64)>>>(h, w + H_OFFS[14], h2, ST(13),  ST(14));
    elem_k<64,8,2,32><<<4096,256>>>(h2, ST(14), o, h);
    ROT();

    // ---- blocks 8,9: 64ch @8x8 ----
    for (int b = 0; b < 2; b++) {
        int la = 15 + 2*b, lb = la + 1;
        convmma_k<64,64,8,1,false><<<T8,256,cm_smem(64,64)>>>(o, w + H_OFFS[la], h,  nullptr, ST(la));
        convmma_k<64,64,8,1,true ><<<T8,256,cm_smem(64,64)>>>(h, w + H_OFFS[lb], h2, ST(la),  ST(lb));
        elem_k<64,8,1,64><<<4096,256>>>(h2, ST(lb), o, h);
        ROT();
    }

    // ---- pool + fc ----
    poolfc_k<<<NB,64>>>(o, Wfc, bfc, y);
#undef ROT
}

// round 6
// speedup vs baseline: 2.8026x; 2.8026x over previous
#include <cuda_runtime.h>
#include <cuda_bf16.h>
#include <cstdint>
#include <cstdio>

// ---------------------------------------------------------------------------
// Problem constants
// ---------------------------------------------------------------------------
#define NB 1024
static const int D_TOT = 267696;

static const int H_OFFS[20] = {0,432,2736,5040,7344,9648,11952,14256,18864,28080,
                               37296,46512,55728,64944,83376,120240,157104,193968,230832,267696};

// ---------------------------------------------------------------------------
// Device scratch
// ---------------------------------------------------------------------------
#define BUF_ELEMS (1024*16*32*32)
__device__ float  g_bufA[BUF_ELEMS];
__device__ float  g_bufB[BUF_ELEMS];
__device__ float  g_bufC[BUF_ELEMS];
__device__ float  g_w[267696];       // natural per-layer layout: [oc][ic][3][3]
__device__ double g_stats[19*64*2];  // per layer, per channel: sum, sumsq

// ---------------------------------------------------------------------------
// helpers
// ---------------------------------------------------------------------------
__host__ __device__ constexpr int pitchf(int K) {
    int p = K;
    while (!((p % 32) == 8 || (p % 32) == 24)) p++;
    return p;
}
__device__ __forceinline__ uint32_t f2tf32(float v) {
    uint32_t u; asm("cvt.rna.tf32.f32 %0, %1;" : "=r"(u) : "f"(v)); return u;
}
// operand order identical to the verified R4 kernel:
// a0=(row g,col t) a1=(row g+8,col t) a2=(row g,col t+4) a3=(row g+8,col t+4)
__device__ __forceinline__ void mma_tf32(float c[4],
                                         uint32_t a0, uint32_t a1, uint32_t a2, uint32_t a3,
                                         uint32_t b0, uint32_t b1) {
    asm volatile(
        "mma.sync.aligned.m16n8k8.row.col.f32.tf32.tf32.f32 "
        "{%0,%1,%2,%3}, {%4,%5,%6,%7}, {%8,%9}, {%0,%1,%2,%3};"
        : "+f"(c[0]), "+f"(c[1]), "+f"(c[2]), "+f"(c[3])
        : "r"(a0), "r"(a1), "r"(a2), "r"(a3), "r"(b0), "r"(b1));
}

// ---------------------------------------------------------------------------
__global__ void zstats_k(double* __restrict__ st) {
    int i = blockIdx.x * blockDim.x + threadIdx.x;
    if (i < 19*64*2) st[i] = 0.0;
}

__global__ void wbuild_k(const float* __restrict__ ow, const float* __restrict__ P,
                         const float* __restrict__ npar, float* __restrict__ wt) {
    __shared__ float s_np[40];
    if (threadIdx.x < 40) s_np[threadIdx.x] = npar[threadIdx.x];
    __syncthreads();
    int d = blockIdx.x * blockDim.x + threadIdx.x;
    if (d >= D_TOT) return;
    float a = ow[d];
#pragma unroll
    for (int j = 0; j < 40; j++)
        a = fmaf(s_np[j], P[(size_t)j * D_TOT + d], a);
    wt[d] = a;
}

// ---------------------------------------------------------------------------
// Direct-from-tile tensor-core conv.
//   CTA = 256 threads = 256 output positions (IMGS images x R rows).
//   Input tile staged once per channel-chunk, channel-last [img][y][icg][x][8],
//   channels within each 8-group permuted so fragment pair (t, t+4) is an
//   adjacent 8-byte pair -> A fragment = one LDS.64 straight from the tile.
//   Logical K order: (ky*3+kx major, channel minor) -> per-step tile offset
//   is a compile-time constant. B staged with matching permutation.
// ---------------------------------------------------------------------------
template<int CINR, int CINP, int COUT, int HIN, int STRIDE, int ICC, int IMGS, bool BN_IN>
__global__ void __launch_bounds__(256)
convt_k(const float* __restrict__ in, const float* __restrict__ wl,
        float* __restrict__ out, const double* __restrict__ st_in,
        double* __restrict__ st_out)
{
    constexpr int W     = HIN / STRIDE;
    constexpr int NPOS  = W * W;
    constexpr int R     = 256 / (W * IMGS);      // out rows per image
    constexpr int SPI   = (IMGS == 1) ? (NPOS / 256) : 1;
    constexpr int TH    = (R - 1) * STRIDE + 3;
    constexpr int TW    = HIN + 2;
    constexpr int NG    = ICC / 8;
    constexpr int NCH   = CINP / ICC;
    constexpr int K     = ICC * 9;
    constexpr int PITCH = pitchf(K);
    constexpr int STEPS = K / 8;
    constexpr int NC    = COUT / 8;
    constexpr int TILEW = IMGS * TH * TW * ICC;

    extern __shared__ float smf[];
    float*    s_sc = smf;
    float*    s_sh = smf + 64;
    uint32_t* s_a  = (uint32_t*)(smf + 128);
    uint32_t* s_b  = s_a + TILEW;

    const int tid = threadIdx.x, wid = tid >> 5, lane = tid & 31;
    const int g = lane >> 2, t = lane & 3;

    const int img0 = (IMGS == 1) ? (blockIdx.x / SPI) : blockIdx.x * IMGS;
    const int r0   = (IMGS == 1) ? (blockIdx.x % SPI) * R : 0;

    if (BN_IN && tid < CINR) {
        const double cnt = 1024.0 * HIN * HIN;
        double mm = st_in[tid*2]   / cnt;
        double vv = st_in[tid*2+1] / cnt - mm * mm;
        float rs = rsqrtf((float)vv + 1e-5f);
        s_sc[tid] = rs;
        s_sh[tid] = (float)(-mm) * rs;
    }
    if (BN_IN) __syncthreads();

    // 4 row-base word offsets into the tile (rows g, g+8, g+16, g+24)
    int basew[4];
#pragma unroll
    for (int i = 0; i < 4; i++) {
        const int p   = wid * 32 + i * 8 + g;
        const int img = p / (R * W);
        const int rem = p - img * (R * W);
        const int y   = rem / W, x = rem - (rem / W) * W;
        basew[i] = (((img * TH + y * STRIDE) * NG) * TW + x * STRIDE) * 8 + 2 * t;
    }

    float acc[2][NC][4];
#pragma unroll
    for (int mt = 0; mt < 2; mt++)
#pragma unroll
        for (int nc = 0; nc < NC; nc++)
#pragma unroll
            for (int i = 0; i < 4; i++) acc[mt][nc][i] = 0.f;

    for (int ch = 0; ch < NCH; ch++) {
        const int ic0 = ch * ICC;
        __syncthreads();

        // ---- stage input tile (channel-last, permuted pairs, tf32 bits) ----
        for (int idx = tid; idx < IMGS * TH * TW; idx += 256) {
            const int img = idx / (TH * TW);
            const int r   = idx - img * (TH * TW);
            const int ty  = r / TW, tx = r - (r / TW) * TW;
            const int yi  = r0 * STRIDE - 1 + ty;
            const int xi  = tx - 1;
            const bool ok = (unsigned)yi < (unsigned)HIN && (unsigned)xi < (unsigned)HIN;
            const float* gb = in + ((size_t)(img0 + img) * CINR + ic0) * HIN * HIN
                                 + yi * HIN + xi;
            uint32_t* dst = s_a + ((img * TH + ty) * NG) * (TW * 8) + tx * 8;
#pragma unroll
            for (int icg = 0; icg < NG; icg++) {
#pragma unroll
                for (int j = 0; j < 4; j++) {
                    const int ia = icg * 8 + j, ib = ia + 4;
                    float va = 0.f, vb = 0.f;
                    if (ok) {
                        if (CINR == CINP || ic0 + ia < CINR) {
                            va = __ldg(gb + ia * HIN * HIN);
                            if (BN_IN) va = fmaxf(fmaf(va, s_sc[ic0+ia], s_sh[ic0+ia]), 0.f);
                        }
                        if (CINR == CINP || ic0 + ib < CINR) {
                            vb = __ldg(gb + ib * HIN * HIN);
                            if (BN_IN) vb = fmaxf(fmaf(vb, s_sc[ic0+ib], s_sh[ic0+ib]), 0.f);
                        }
                    }
                    dst[icg * (TW * 8) + 2*j]     = f2tf32(va);
                    dst[icg * (TW * 8) + 2*j + 1] = f2tf32(vb);
                }
            }
        }

        // ---- stage B (row per oc, K permuted to match) ----
        for (int idx = tid; idx < COUT * K; idx += 256) {
            const int oc = idx / K;
            const int c  = idx - oc * K;
            const int s  = c >> 3, u = c & 7;
            const int k  = s / NG, icg = s - (s / NG) * NG;
            const int ic = ic0 + icg * 8 + u;
            float v = (CINR == CINP || ic < CINR) ? wl[(oc * CINR + ic) * 9 + k] : 0.f;
            const int phys = (u < 4) ? 2*u : 2*(u-4) + 1;
            s_b[oc * PITCH + s * 8 + phys] = f2tf32(v);
        }
        __syncthreads();

        // ---- MMA over STEPS k-slices ----
#pragma unroll
        for (int s = 0; s < STEPS; s++) {
            const int k   = s / NG;
            const int icg = s - k * NG;
            const int ky  = k / 3, kx = k - (k / 3) * 3;
            const int off = ((ky * NG + icg) * TW + kx) * 8;
            uint2 A0 = *(const uint2*)(s_a + basew[0] + off);
            uint2 A1 = *(const uint2*)(s_a + basew[1] + off);
            uint2 A2 = *(const uint2*)(s_a + basew[2] + off);
            uint2 A3 = *(const uint2*)(s_a + basew[3] + off);
#pragma unroll
            for (int nc = 0; nc < NC; nc++) {
                uint2 B = *(const uint2*)(s_b + (nc * 8 + g) * PITCH + s * 8 + 2 * t);
                mma_tf32(acc[0][nc], A0.x, A1.x, A0.y, A1.y, B.x, B.y);
                mma_tf32(acc[1][nc], A2.x, A3.x, A2.y, A3.y, B.x, B.y);
            }
        }
    }

    // ---- epilogue: frags -> smem [COUT][256] -> coalesced NCHW + BN stats ----
    __syncthreads();
    float* s_st  = smf + 128;
    float* s_red = s_st + COUT * 256;
#pragma unroll
    for (int mt = 0; mt < 2; mt++)
#pragma unroll
        for (int nc = 0; nc < NC; nc++) {
            const int cb = nc * 8 + 2 * t;
            const int p0 = wid * 32 + mt * 16 + g;
            s_st[(cb + 0) * 256 + p0]     = acc[mt][nc][0];
            s_st[(cb + 1) * 256 + p0]     = acc[mt][nc][1];
            s_st[(cb + 0) * 256 + p0 + 8] = acc[mt][nc][2];
            s_st[(cb + 1) * 256 + p0 + 8] = acc[mt][nc][3];
        }
    __syncthreads();

    for (int idx = tid; idx < COUT * 256; idx += 256) {
        const int c   = idx >> 8;
        const int lp  = idx & 255;
        const int img = lp / (R * W);
        const int rem = lp - img * (R * W);
        const int y   = r0 + rem / W;
        const int x   = rem - (rem / W) * W;
        out[((size_t)(img0 + img) * COUT + c) * NPOS + y * W + x] = s_st[c * 256 + lp];
    }

#pragma unroll 1
    for (int c = 0; c < COUT; c++) {
        float v = s_st[c * 256 + tid];
        float s = v, q = v * v;
#pragma unroll
        for (int off = 16; off; off >>= 1) {
            s += __shfl_down_sync(0xffffffffu, s, off);
            q += __shfl_down_sync(0xffffffffu, q, off);
        }
        if (lane == 0) {
            s_red[(wid * COUT + c) * 2 + 0] = s;
            s_red[(wid * COUT + c) * 2 + 1] = q;
        }
    }
    __syncthreads();
    if (tid < COUT) {
        float s = 0.f, q = 0.f;
#pragma unroll
        for (int w8 = 0; w8 < 8; w8++) {
            s += s_red[(w8 * COUT + tid) * 2 + 0];
            q += s_red[(w8 * COUT + tid) * 2 + 1];
        }
        atomicAdd(&st_out[tid * 2 + 0], (double)s);
        atomicAdd(&st_out[tid * 2 + 1], (double)q);
    }
}

// ---------------------------------------------------------------------------
// Residual epilogue, float4-vectorized: out = relu( bn(h) + shortcut(prev) )
// ---------------------------------------------------------------------------
template<int C, int H, int MODE, int CPREV>
__global__ void __launch_bounds__(256)
elem_k(const float* __restrict__ h, const double* __restrict__ st,
       const float* __restrict__ prev, float* __restrict__ out)
{
    __shared__ float s_sc[C], s_sh[C];
    if (threadIdx.x < C) {
        const double cnt = 1024.0 * H * H;
        double m = st[threadIdx.x*2]   / cnt;
        double v = st[threadIdx.x*2+1] / cnt - m * m;
        float rs = rsqrtf((float)v + 1e-5f);
        s_sc[threadIdx.x] = rs;
        s_sh[threadIdx.x] = (float)(-m) * rs;
    }
    __syncthreads();

    const int idx4 = blockIdx.x * 256 + threadIdx.x;
    const int e    = idx4 * 4;
    if (e >= 1024 * C * H * H) return;
    const int hw = e % (H * H);
    const int c  = (e / (H * H)) % C;
    const int n  = e / (H * H * C);

    const float sc = s_sc[c], sh = s_sh[c];
    float4 hv = *(const float4*)(h + e);
    float4 r;
    r.x = fmaf(hv.x, sc, sh); r.y = fmaf(hv.y, sc, sh);
    r.z = fmaf(hv.z, sc, sh); r.w = fmaf(hv.w, sc, sh);

    if (MODE == 1) {
        float4 pv = *(const float4*)(prev + e);
        r.x += pv.x; r.y += pv.y; r.z += pv.z; r.w += pv.w;
    } else if (MODE == 2) {
        const int pc = c - (C - CPREV) / 2;
        if (pc >= 0 && pc < CPREV) {
            const int y = hw / H, x = hw - (hw / H) * H;
            const float* pb = prev + ((size_t)n * CPREV + pc) * (4 * H * H)
                                   + (2 * y) * (2 * H) + 2 * x;
            r.x += pb[0]; r.y += pb[2]; r.z += pb[4]; r.w += pb[6];
        }
    }
    r.x = fmaxf(r.x, 0.f); r.y = fmaxf(r.y, 0.f);
    r.z = fmaxf(r.z, 0.f); r.w = fmaxf(r.w, 0.f);
    *(float4*)(out + e) = r;
}

// ---------------------------------------------------------------------------
// Global average pool (8x8) + FC 64->10
// ---------------------------------------------------------------------------
__global__ void __launch_bounds__(64)
poolfc_k(const float* __restrict__ in, const float* __restrict__ Wfc,
         const float* __restrict__ bfc, float* __restrict__ out)
{
    __shared__ float pooled[64];
    const int n = blockIdx.x, t = threadIdx.x;
    const float* p = in + (size_t)n * 64 * 64;
    float s = 0.f;
#pragma unroll
    for (int i = 0; i < 64; i++) s += p[t * 64 + i];
    pooled[t] = s * (1.f / 64.f);
    __syncthreads();
    if (t < 10) {
        float a = bfc[t];
#pragma unroll
        for (int c = 0; c < 64; c++) a = fmaf(Wfc[t * 64 + c], pooled[c], a);
        out[n * 10 + t] = a;
    }
}

// ---------------------------------------------------------------------------
// Host-side smem size (mirror of kernel constants)
// ---------------------------------------------------------------------------
static constexpr int cm2(int CINP, int COUT, int HIN, int STRIDE, int ICC, int IMGS) {
    int W  = HIN / STRIDE;
    int R  = 256 / (W * IMGS);
    int TH = (R - 1) * STRIDE + 3;
    int TW = HIN + 2;
    int K  = ICC * 9;
    int P  = pitchf(K);
    int tile = IMGS * TH * TW * ICC;
    int p1 = tile + COUT * P;
    int p2 = COUT * 256 + 16 * COUT;
    int m  = (p1 > p2) ? p1 : p2;
    return (128 + m) * 4;
}

extern "C" void kernel_launch(void* const* d_in, const int* in_sizes, int n_in,
                              void* d_out, int out_size)
{
    (void)in_sizes; (void)n_in; (void)out_size;
    const float* x   = (const float*)d_in[0];
    const float* ow  = (const float*)d_in[1];
    const float* P   = (const float*)d_in[2];
    const float* npar= (const float*)d_in[3];
    const float* Wfc = (const float*)d_in[4];
    const float* bfc = (const float*)d_in[5];
    float* y = (float*)d_out;

    float *A, *B, *C, *w; double* st;
    cudaGetSymbolAddress((void**)&A, g_bufA);
    cudaGetSymbolAddress((void**)&B, g_bufB);
    cudaGetSymbolAddress((void**)&C, g_bufC);
    cudaGetSymbolAddress((void**)&w, g_w);
    cudaGetSymbolAddress((void**)&st, g_stats);

    cudaFuncSetAttribute(convt_k< 3, 8,16,32,1, 8,1,false>, cudaFuncAttributeMaxDynamicSharedMemorySize, cm2( 8,16,32,1, 8,1));
    cudaFuncSetAttribute(convt_k<16,16,16,32,1,16,1,false>, cudaFuncAttributeMaxDynamicSharedMemorySize, cm2(16,16,32,1,16,1));
    cudaFuncSetAttribute(convt_k<16,16,16,32,1,16,1,true >, cudaFuncAttributeMaxDynamicSharedMemorySize, cm2(16,16,32,1,16,1));
    cudaFuncSetAttribute(convt_k<16,16,32,32,2, 8,1,false>, cudaFuncAttributeMaxDynamicSharedMemorySize, cm2(16,32,32,2, 8,1));
    cudaFuncSetAttribute(convt_k<32,32,32,16,1,16,1,true >, cudaFuncAttributeMaxDynamicSharedMemorySize, cm2(32,32,16,1,16,1));
    cudaFuncSetAttribute(convt_k<32,32,32,16,1,16,1,false>, cudaFuncAttributeMaxDynamicSharedMemorySize, cm2(32,32,16,1,16,1));
    cudaFuncSetAttribute(convt_k<32,32,64,16,2, 8,4,false>, cudaFuncAttributeMaxDynamicSharedMemorySize, cm2(32,64,16,2, 8,4));
    cudaFuncSetAttribute(convt_k<64,64,64, 8,1,16,4,true >, cudaFuncAttributeMaxDynamicSharedMemorySize, cm2(64,64, 8,1,16,4));
    cudaFuncSetAttribute(convt_k<64,64,64, 8,1,16,4,false>, cudaFuncAttributeMaxDynamicSharedMemorySize, cm2(64,64, 8,1,16,4));

    auto ST = [&](int l) { return st + l * 128; };

    zstats_k<<<(19*64*2 + 255)/256, 256>>>(st);
    wbuild_k<<<(D_TOT + 255)/256, 256>>>(ow, P, npar, w);

    // ---- layer 0 ----
    convt_k<3,8,16,32,1,8,1,false><<<4096,256,cm2(8,16,32,1,8,1)>>>(x, w + H_OFFS[0], A, nullptr, ST(0));
    elem_k<16,32,0,16><<<16384,256>>>(A, ST(0), nullptr, B);

    float* o  = B;
    float* h  = C;
    float* h2 = A;
#define ROT() { float* t = o; o = h; h = h2; h2 = t; }

    // ---- stage 1: 16ch @32x32 ----
    for (int b = 0; b < 3; b++) {
        int la = 1 + 2*b, lb = la + 1;
        convt_k<16,16,16,32,1,16,1,false><<<4096,256,cm2(16,16,32,1,16,1)>>>(o, w + H_OFFS[la], h,  nullptr, ST(la));
        convt_k<16,16,16,32,1,16,1,true ><<<4096,256,cm2(16,16,32,1,16,1)>>>(h, w + H_OFFS[lb], h2, ST(la),  ST(lb));
        elem_k<16,32,1,16><<<16384,256>>>(h2, ST(lb), o, h);
        ROT();
    }

    // ---- block 4: 16->32, stride 2 ----
    convt_k<16,16,32,32,2,8,1,false><<<1024,256,cm2(16,32,32,2,8,1)>>>(o, w + H_OFFS[7], h,  nullptr, ST(7));
    convt_k<32,32,32,16,1,16,1,true ><<<1024,256,cm2(32,32,16,1,16,1)>>>(h, w + H_OFFS[8], h2, ST(7),   ST(8));
    elem_k<32,16,2,16><<<8192,256>>>(h2, ST(8), o, h);
    ROT();

    // ---- blocks 5,6: 32ch @16x16 ----
    for (int b = 0; b < 2; b++) {
        int la = 9 + 2*b, lb = la + 1;
        convt_k<32,32,32,16,1,16,1,false><<<1024,256,cm2(32,32,16,1,16,1)>>>(o, w + H_OFFS[la], h,  nullptr, ST(la));
        convt_k<32,32,32,16,1,16,1,true ><<<1024,256,cm2(32,32,16,1,16,1)>>>(h, w + H_OFFS[lb], h2, ST(la),  ST(lb));
        elem_k<32,16,1,32><<<8192,256>>>(h2, ST(lb), o, h);
        ROT();
    }

    // ---- block 7: 32->64, stride 2 ----
    convt_k<32,32,64,16,2,8,4,false><<<256,256,cm2(32,64,16,2,8,4)>>>(o, w + H_OFFS[13], h,  nullptr, ST(13));
    convt_k<64,64,64, 8,1,16,4,true ><<<256,256,cm2(64,64,8,1,16,4)>>>(h, w + H_OFFS[14], h2, ST(13),  ST(14));
    elem_k<64,8,2,32><<<4096,256>>>(h2, ST(14), o, h);
    ROT();

    // ---- blocks 8,9: 64ch @8x8 ----
    for (int b = 0; b < 2; b++) {
        int la = 15 + 2*b, lb = la + 1;
        convt_k<64,64,64,8,1,16,4,false><<<256,256,cm2(64,64,8,1,16,4)>>>(o, w + H_OFFS[la], h,  nullptr, ST(la));
        convt_k<64,64,64,8,1,16,4,true ><<<256,256,cm2(64,64,8,1,16,4)>>>(h, w + H_OFFS[lb], h2, ST(la),  ST(lb));
        elem_k<64,8,1,64><<<4096,256>>>(h2, ST(lb), o, h);
        ROT();
    }

    // ---- pool + fc ----
    poolfc_k<<<NB,64>>>(o, Wfc, bfc, y);
#undef ROT
}

// round 7
// speedup vs baseline: 3.3257x; 1.1866x over previous
#include <cuda_runtime.h>
#include <cuda_bf16.h>
#include <cstdint>
#include <cstdio>

// ---------------------------------------------------------------------------
// Problem constants
// ---------------------------------------------------------------------------
#define NB 1024
static const int D_TOT = 267696;

static const int H_OFFS[20] = {0,432,2736,5040,7344,9648,11952,14256,18864,28080,
                               37296,46512,55728,64944,83376,120240,157104,193968,230832,267696};

// permuted tf32 weight buffer offsets (see wperm_k)
static const int PO_H[19] = {0,1152,3584,6016,8448,10880,13312,15744,20352,30080,
                             39808,49536,59264,68992,87424,126336,165248,204160,243072};
#define WP_TOT 281984

__constant__ int c_PO[19]   = {0,1152,3584,6016,8448,10880,13312,15744,20352,30080,
                               39808,49536,59264,68992,87424,126336,165248,204160,243072};
__constant__ int c_WOFF[19] = {0,432,2736,5040,7344,9648,11952,14256,18864,28080,
                               37296,46512,55728,64944,83376,120240,157104,193968,230832};
__constant__ int c_LCIN[19]  = {3,16,16,16,16,16,16,16,32,32,32,32,32,32,64,64,64,64,64};
__constant__ int c_LICC[19]  = {8,16,16,16,16,16,16,8,16,16,16,16,16,8,16,16,16,16,16};
__constant__ int c_LCOUT[19] = {16,16,16,16,16,16,16,32,32,32,32,32,32,64,64,64,64,64,64};
__constant__ int c_LPITCH[19]= {72,152,152,152,152,152,152,72,152,152,152,152,152,72,152,152,152,152,152};

// ---------------------------------------------------------------------------
// Device scratch
// ---------------------------------------------------------------------------
#define BUF_ELEMS (1024*16*32*32)
__device__ float    g_bufA[BUF_ELEMS];
__device__ float    g_bufB[BUF_ELEMS];
__device__ float    g_bufC[BUF_ELEMS];
__device__ float    g_bufD[BUF_ELEMS];
__device__ float    g_w[267696];       // natural per-layer layout: [oc][ic][3][3]
__device__ uint32_t g_wp[WP_TOT];      // permuted tf32 smem-image weights
__device__ double   g_stats[19*64*2];  // per layer, per channel: sum, sumsq

// ---------------------------------------------------------------------------
// helpers
// ---------------------------------------------------------------------------
__host__ __device__ constexpr int pitchf(int K) {
    int p = K;
    while (!((p % 32) == 8 || (p % 32) == 24)) p++;
    return p;
}
__device__ __forceinline__ uint32_t f2tf32(float v) {
    uint32_t u; asm("cvt.rna.tf32.f32 %0, %1;" : "=r"(u) : "f"(v)); return u;
}
__device__ __forceinline__ void mma_tf32(float c[4],
                                         uint32_t a0, uint32_t a1, uint32_t a2, uint32_t a3,
                                         uint32_t b0, uint32_t b1) {
    asm volatile(
        "mma.sync.aligned.m16n8k8.row.col.f32.tf32.tf32.f32 "
        "{%0,%1,%2,%3}, {%4,%5,%6,%7}, {%8,%9}, {%0,%1,%2,%3};"
        : "+f"(c[0]), "+f"(c[1]), "+f"(c[2]), "+f"(c[3])
        : "r"(a0), "r"(a1), "r"(a2), "r"(a3), "r"(b0), "r"(b1));
}

// ---------------------------------------------------------------------------
__global__ void zstats_k(double* __restrict__ st) {
    int i = blockIdx.x * blockDim.x + threadIdx.x;
    if (i < 19*64*2) st[i] = 0.0;
}

__global__ void wbuild_k(const float* __restrict__ ow, const float* __restrict__ P,
                         const float* __restrict__ npar, float* __restrict__ wt) {
    __shared__ float s_np[40];
    if (threadIdx.x < 40) s_np[threadIdx.x] = npar[threadIdx.x];
    __syncthreads();
    int d = blockIdx.x * blockDim.x + threadIdx.x;
    if (d >= D_TOT) return;
    float a = ow[d];
#pragma unroll
    for (int j = 0; j < 40; j++)
        a = fmaf(s_np[j], P[(size_t)j * D_TOT + d], a);
    wt[d] = a;
}

// Permute weights into the exact smem image the conv consumes:
// per layer, per chunk ch: [oc][PITCH words], slot s*8+phys where
// s = k*NG + icg, phys = (u<4) ? 2u : 2(u-4)+1, ic = ch*ICC + icg*8 + u.
__global__ void wperm_k(const float* __restrict__ w, uint32_t* __restrict__ wp) {
    int i = blockIdx.x * blockDim.x + threadIdx.x;
    if (i >= WP_TOT) return;
    int l = 18;
    while (l > 0 && i < c_PO[l]) l--;
    const int r     = i - c_PO[l];
    const int CINR  = c_LCIN[l];
    const int ICC   = c_LICC[l];
    const int COUT  = c_LCOUT[l];
    const int PITCH = c_LPITCH[l];
    const int K     = ICC * 9;
    const int NG    = ICC / 8;
    const int cs    = COUT * PITCH;
    const int ch    = r / cs;
    const int r2    = r - ch * cs;
    const int oc    = r2 / PITCH;
    const int pos   = r2 - oc * PITCH;
    float v = 0.f;
    if (pos < K) {
        const int s    = pos >> 3, phys = pos & 7;
        const int u    = (phys & 1) ? (phys >> 1) + 4 : (phys >> 1);
        const int k    = s / NG, icg = s - (s / NG) * NG;
        const int ic   = ch * ICC + icg * 8 + u;
        if (ic < CINR) v = w[c_WOFF[l] + (oc * CINR + ic) * 9 + k];
    }
    wp[i] = f2tf32(v);
}

// ---------------------------------------------------------------------------
// Direct-from-tile tensor-core conv with fused input transform.
//  MODE 0: plain input (x)
//  MODE 1: relu(bn(in))                              [conv-b, and block1 conv-a]
//  MODE 2: relu(bn(in) + prev)            (identity shortcut, CPREV==CINR)
//  MODE 3: relu(bn(in) + padded/strided prev)  (prev: CPREV ch, spatial 2*HIN)
//  WF: write the transformed activation to `fused` during staging.
// ---------------------------------------------------------------------------
template<int CINR, int CINP, int COUT, int HIN, int STRIDE, int ICC, int IMGS,
         int MODE, int CPREV, bool WF>
__global__ void __launch_bounds__(256)
convt_k(const float* __restrict__ in, const uint32_t* __restrict__ wpb,
        float* __restrict__ out, const double* __restrict__ st_in,
        double* __restrict__ st_out, const float* __restrict__ prev,
        float* __restrict__ fused)
{
    constexpr int W     = HIN / STRIDE;
    constexpr int NPOS  = W * W;
    constexpr int R     = 256 / (W * IMGS);
    constexpr int SPI   = (IMGS == 1) ? (NPOS / 256) : 1;
    constexpr int TH    = (R - 1) * STRIDE + 3;
    constexpr int TW    = HIN + 2;
    constexpr int NG    = ICC / 8;
    constexpr int NCH   = CINP / ICC;
    constexpr int K     = ICC * 9;
    constexpr int PITCH = pitchf(K);
    constexpr int STEPS = K / 8;
    constexpr int NC    = COUT / 8;
    constexpr int TILEW = IMGS * TH * TW * ICC;
    constexpr int PADF  = (MODE == 3) ? (CINR - CPREV) / 2 : 0;

    extern __shared__ float smf[];
    float*    s_sc = smf;
    float*    s_sh = smf + 64;
    uint32_t* s_a  = (uint32_t*)(smf + 128);
    uint32_t* s_b  = s_a + TILEW;

    const int tid = threadIdx.x, wid = tid >> 5, lane = tid & 31;
    const int g = lane >> 2, t = lane & 3;

    const int img0 = (IMGS == 1) ? (blockIdx.x / SPI) : blockIdx.x * IMGS;
    const int r0   = (IMGS == 1) ? (blockIdx.x % SPI) * R : 0;

    if (MODE >= 1 && tid < CINR) {
        const double cnt = 1024.0 * HIN * HIN;
        double mm = st_in[tid*2]   / cnt;
        double vv = st_in[tid*2+1] / cnt - mm * mm;
        float rs = rsqrtf((float)vv + 1e-5f);
        s_sc[tid] = rs;
        s_sh[tid] = (float)(-mm) * rs;
    }
    if (MODE >= 1) __syncthreads();

    // 4 row-base word offsets into the tile (rows g, g+8, g+16, g+24)
    int basew[4];
#pragma unroll
    for (int i = 0; i < 4; i++) {
        const int p   = wid * 32 + i * 8 + g;
        const int img = p / (R * W);
        const int rem = p - img * (R * W);
        const int y   = rem / W, x = rem - (rem / W) * W;
        basew[i] = (((img * TH + y * STRIDE) * NG) * TW + x * STRIDE) * 8 + 2 * t;
    }

    float acc[2][NC][4];
#pragma unroll
    for (int mt = 0; mt < 2; mt++)
#pragma unroll
        for (int nc = 0; nc < NC; nc++)
#pragma unroll
            for (int i = 0; i < 4; i++) acc[mt][nc][i] = 0.f;

    for (int ch = 0; ch < NCH; ch++) {
        const int ic0 = ch * ICC;
        __syncthreads();

        // ---- stage input tile (transform fused in) ----
        for (int idx = tid; idx < IMGS * TH * TW; idx += 256) {
            const int img = idx / (TH * TW);
            const int rr  = idx - img * (TH * TW);
            const int ty  = rr / TW, tx = rr - (rr / TW) * TW;
            const int yi  = r0 * STRIDE - 1 + ty;
            const int xi  = tx - 1;
            const bool ok = (unsigned)yi < (unsigned)HIN && (unsigned)xi < (unsigned)HIN;
            const int  n  = img0 + img;
            const float* gb = in + ((size_t)n * CINR + ic0) * HIN * HIN + yi * HIN + xi;
            const float* pv = nullptr;
            if (MODE == 2)
                pv = prev + ((size_t)n * CPREV) * HIN * HIN + yi * HIN + xi;
            if (MODE == 3)
                pv = prev + ((size_t)n * CPREV) * (4 * HIN * HIN)
                          + (2 * yi) * (2 * HIN) + 2 * xi;
            float* fb = nullptr;
            if (WF) fb = fused + ((size_t)n * CINR) * HIN * HIN + yi * HIN + xi;

            uint32_t* dst = s_a + ((img * TH + ty) * NG) * (TW * 8) + tx * 8;
#pragma unroll
            for (int icg = 0; icg < NG; icg++) {
#pragma unroll
                for (int j = 0; j < 4; j++) {
                    const int ia = icg * 8 + j, ib = ia + 4;
                    float va = 0.f, vb = 0.f;
                    if (ok) {
#pragma unroll
                        for (int hh = 0; hh < 2; hh++) {
                            const int ii = hh ? ib : ia;
                            const int ic = ic0 + ii;
                            float v = 0.f;
                            if (CINR == CINP || ic < CINR) {
                                v = __ldg(gb + ii * HIN * HIN);
                                if (MODE >= 1) v = fmaf(v, s_sc[ic], s_sh[ic]);
                                if (MODE == 2) v += __ldg(pv + ic * HIN * HIN);
                                if (MODE == 3) {
                                    const int pc = ic - PADF;
                                    if (pc >= 0 && pc < CPREV)
                                        v += __ldg(pv + pc * (4 * HIN * HIN));
                                }
                                if (MODE >= 1) v = fmaxf(v, 0.f);
                                if (WF) fb[(size_t)ic * HIN * HIN] = v;
                            }
                            if (hh) vb = v; else va = v;
                        }
                    }
                    dst[icg * (TW * 8) + 2*j]     = f2tf32(va);
                    dst[icg * (TW * 8) + 2*j + 1] = f2tf32(vb);
                }
            }
        }

        // ---- stage B: plain vector copy of pre-permuted tf32 weights ----
        {
            const uint4* wb = (const uint4*)(wpb + ch * (COUT * PITCH));
            uint4* sb4 = (uint4*)s_b;
#pragma unroll 4
            for (int idx = tid; idx < COUT * PITCH / 4; idx += 256)
                sb4[idx] = wb[idx];
        }
        __syncthreads();

        // ---- MMA over STEPS k-slices ----
#pragma unroll
        for (int s = 0; s < STEPS; s++) {
            const int k   = s / NG;
            const int icg = s - k * NG;
            const int ky  = k / 3, kx = k - (k / 3) * 3;
            const int off = ((ky * NG + icg) * TW + kx) * 8;
            uint2 A0 = *(const uint2*)(s_a + basew[0] + off);
            uint2 A1 = *(const uint2*)(s_a + basew[1] + off);
            uint2 A2 = *(const uint2*)(s_a + basew[2] + off);
            uint2 A3 = *(const uint2*)(s_a + basew[3] + off);
#pragma unroll
            for (int nc = 0; nc < NC; nc++) {
                uint2 B = *(const uint2*)(s_b + (nc * 8 + g) * PITCH + s * 8 + 2 * t);
                mma_tf32(acc[0][nc], A0.x, A1.x, A0.y, A1.y, B.x, B.y);
                mma_tf32(acc[1][nc], A2.x, A3.x, A2.y, A3.y, B.x, B.y);
            }
        }
    }

    __syncthreads();   // mainloop smem regions free from here
    float* s_st  = smf + 128;
    float* s_red = s_st + COUT * 256;   // [8 warps][COUT][2]

    // ---- BN stats straight from accumulators ----
#pragma unroll
    for (int nc = 0; nc < NC; nc++) {
        float s0 = acc[0][nc][0] + acc[0][nc][2] + acc[1][nc][0] + acc[1][nc][2];
        float s1 = acc[0][nc][1] + acc[0][nc][3] + acc[1][nc][1] + acc[1][nc][3];
        float q0 = acc[0][nc][0]*acc[0][nc][0] + acc[0][nc][2]*acc[0][nc][2]
                 + acc[1][nc][0]*acc[1][nc][0] + acc[1][nc][2]*acc[1][nc][2];
        float q1 = acc[0][nc][1]*acc[0][nc][1] + acc[0][nc][3]*acc[0][nc][3]
                 + acc[1][nc][1]*acc[1][nc][1] + acc[1][nc][3]*acc[1][nc][3];
#pragma unroll
        for (int off = 4; off < 32; off <<= 1) {
            s0 += __shfl_xor_sync(0xffffffffu, s0, off);
            s1 += __shfl_xor_sync(0xffffffffu, s1, off);
            q0 += __shfl_xor_sync(0xffffffffu, q0, off);
            q1 += __shfl_xor_sync(0xffffffffu, q1, off);
        }
        if (lane < 4) {
            const int cb = nc * 8 + 2 * lane;
            s_red[(wid * COUT + cb)     * 2 + 0] = s0;
            s_red[(wid * COUT + cb)     * 2 + 1] = q0;
            s_red[(wid * COUT + cb + 1) * 2 + 0] = s1;
            s_red[(wid * COUT + cb + 1) * 2 + 1] = q1;
        }
    }

    // ---- frags -> smem staging [COUT][256] ----
#pragma unroll
    for (int mt = 0; mt < 2; mt++)
#pragma unroll
        for (int nc = 0; nc < NC; nc++) {
            const int cb = nc * 8 + 2 * t;
            const int p0 = wid * 32 + mt * 16 + g;
            s_st[(cb + 0) * 256 + p0]     = acc[mt][nc][0];
            s_st[(cb + 1) * 256 + p0]     = acc[mt][nc][1];
            s_st[(cb + 0) * 256 + p0 + 8] = acc[mt][nc][2];
            s_st[(cb + 1) * 256 + p0 + 8] = acc[mt][nc][3];
        }
    __syncthreads();

    // coalesced NCHW store
    for (int idx = tid; idx < COUT * 256; idx += 256) {
        const int c   = idx >> 8;
        const int lp  = idx & 255;
        const int img = lp / (R * W);
        const int rem = lp - img * (R * W);
        const int y   = r0 + rem / W;
        const int x   = rem - (rem / W) * W;
        out[((size_t)(img0 + img) * COUT + c) * NPOS + y * W + x] = s_st[c * 256 + lp];
    }

    if (tid < COUT) {
        float s = 0.f, q = 0.f;
#pragma unroll
        for (int w8 = 0; w8 < 8; w8++) {
            s += s_red[(w8 * COUT + tid) * 2 + 0];
            q += s_red[(w8 * COUT + tid) * 2 + 1];
        }
        atomicAdd(&st_out[tid * 2 + 0], (double)s);
        atomicAdd(&st_out[tid * 2 + 1], (double)q);
    }
}

// ---------------------------------------------------------------------------
// Fused final residual + global average pool (8x8) + FC 64->10
// ---------------------------------------------------------------------------
__global__ void __launch_bounds__(64)
poolfc_k(const float* __restrict__ h2, const double* __restrict__ st,
         const float* __restrict__ prev, const float* __restrict__ Wfc,
         const float* __restrict__ bfc, float* __restrict__ out)
{
    __shared__ float pooled[64];
    const int n = blockIdx.x, t = threadIdx.x;
    const double cnt = 1024.0 * 64.0;
    double m = st[t*2] / cnt;
    double v = st[t*2+1] / cnt - m * m;
    const float sc = rsqrtf((float)v + 1e-5f);
    const float sh = (float)(-m) * sc;
    const float* hp = h2   + (size_t)n * 64 * 64 + t * 64;
    const float* pp = prev + (size_t)n * 64 * 64 + t * 64;
    float s = 0.f;
#pragma unroll
    for (int i = 0; i < 64; i++)
        s += fmaxf(fmaf(hp[i], sc, sh) + pp[i], 0.f);
    pooled[t] = s * (1.f / 64.f);
    __syncthreads();
    if (t < 10) {
        float a = bfc[t];
#pragma unroll
        for (int c = 0; c < 64; c++) a = fmaf(Wfc[t * 64 + c], pooled[c], a);
        out[n * 10 + t] = a;
    }
}

// ---------------------------------------------------------------------------
// Host-side smem size (mirror of kernel constants)
// ---------------------------------------------------------------------------
static constexpr int cm2(int CINP, int COUT, int HIN, int STRIDE, int ICC, int IMGS) {
    int W  = HIN / STRIDE;
    int R  = 256 / (W * IMGS);
    int TH = (R - 1) * STRIDE + 3;
    int TW = HIN + 2;
    int K  = ICC * 9;
    int P  = pitchf(K);
    int tile = IMGS * TH * TW * ICC;
    int p1 = tile + COUT * P;
    int p2 = COUT * 256 + 16 * COUT;
    int m  = (p1 > p2) ? p1 : p2;
    return (128 + m) * 4;
}

extern "C" void kernel_launch(void* const* d_in, const int* in_sizes, int n_in,
                              void* d_out, int out_size)
{
    (void)in_sizes; (void)n_in; (void)out_size;
    const float* x   = (const float*)d_in[0];
    const float* ow  = (const float*)d_in[1];
    const float* P   = (const float*)d_in[2];
    const float* npar= (const float*)d_in[3];
    const float* Wfc = (const float*)d_in[4];
    const float* bfc = (const float*)d_in[5];
    float* y = (float*)d_out;

    float *A, *B, *C, *D, *w; uint32_t* wp; double* st;
    cudaGetSymbolAddress((void**)&A,  g_bufA);
    cudaGetSymbolAddress((void**)&B,  g_bufB);
    cudaGetSymbolAddress((void**)&C,  g_bufC);
    cudaGetSymbolAddress((void**)&D,  g_bufD);
    cudaGetSymbolAddress((void**)&w,  g_w);
    cudaGetSymbolAddress((void**)&wp, g_wp);
    cudaGetSymbolAddress((void**)&st, g_stats);

    // instantiation helpers
    #define SETSM(FN, CINP_, COUT_, HIN_, STRIDE_, ICC_, IMGS_) \
        cudaFuncSetAttribute(FN, cudaFuncAttributeMaxDynamicSharedMemorySize, \
                             cm2(CINP_, COUT_, HIN_, STRIDE_, ICC_, IMGS_))

    auto I0  = convt_k< 3, 8,16,32,1, 8,1,0, 0,false>; SETSM(I0,  8,16,32,1, 8,1);
    auto I1  = convt_k<16,16,16,32,1,16,1,1, 0,true >; SETSM(I1, 16,16,32,1,16,1);
    auto I2  = convt_k<16,16,16,32,1,16,1,1, 0,false>; SETSM(I2, 16,16,32,1,16,1);
    auto I3  = convt_k<16,16,16,32,1,16,1,2,16,true >; SETSM(I3, 16,16,32,1,16,1);
    auto I4  = convt_k<16,16,32,32,2, 8,1,2,16,true >; SETSM(I4, 16,32,32,2, 8,1);
    auto I5  = convt_k<32,32,32,16,1,16,1,1, 0,false>; SETSM(I5, 32,32,16,1,16,1);
    auto I6  = convt_k<32,32,32,16,1,16,1,3,16,true >; SETSM(I6, 32,32,16,1,16,1);
    auto I7  = convt_k<32,32,32,16,1,16,1,2,32,true >; SETSM(I7, 32,32,16,1,16,1);
    auto I8  = convt_k<32,32,64,16,2, 8,4,2,32,true >; SETSM(I8, 32,64,16,2, 8,4);
    auto I9  = convt_k<64,64,64, 8,1,16,4,1, 0,false>; SETSM(I9, 64,64, 8,1,16,4);
    auto I10 = convt_k<64,64,64, 8,1,16,4,3,32,true >; SETSM(I10,64,64, 8,1,16,4);
    auto I11 = convt_k<64,64,64, 8,1,16,4,2,64,true >; SETSM(I11,64,64, 8,1,16,4);
    #undef SETSM

    auto ST = [&](int l) { return st + l * 128; };
    auto WL = [&](int l) { return wp + PO_H[l]; };

    zstats_k<<<(19*64*2 + 255)/256, 256>>>(st);
    wbuild_k<<<(D_TOT + 255)/256, 256>>>(ow, P, npar, w);
    wperm_k<<<(WP_TOT + 255)/256, 256>>>(w, wp);

    const int S1 = cm2( 8,16,32,1, 8,1);
    const int S2 = cm2(16,16,32,1,16,1);
    const int S3 = cm2(16,32,32,2, 8,1);
    const int S4 = cm2(32,32,16,1,16,1);
    const int S5 = cm2(32,64,16,2, 8,4);
    const int S6 = cm2(64,64, 8,1,16,4);

    // layer 0
    I0 <<<4096,256,S1>>>(x, WL(0), A, nullptr, ST(0), nullptr, nullptr);
    // block 1
    I1 <<<4096,256,S2>>>(A, WL(1), B, ST(0),  ST(1), nullptr, C);
    I2 <<<4096,256,S2>>>(B, WL(2), A, ST(1),  ST(2), nullptr, nullptr);
    // block 2
    I3 <<<4096,256,S2>>>(A, WL(3), B, ST(2),  ST(3), C, D);
    I2 <<<4096,256,S2>>>(B, WL(4), C, ST(3),  ST(4), nullptr, nullptr);
    // block 3
    I3 <<<4096,256,S2>>>(C, WL(5), B, ST(4),  ST(5), D, A);
    I2 <<<4096,256,S2>>>(B, WL(6), D, ST(5),  ST(6), nullptr, nullptr);
    // block 4 (16->32, stride 2)
    I4 <<<1024,256,S3>>>(D, WL(7), B, ST(6),  ST(7), A, C);
    I5 <<<1024,256,S4>>>(B, WL(8), A, ST(7),  ST(8), nullptr, nullptr);
    // block 5 (MODE3 pad shortcut, prev 16ch@32)
    I6 <<<1024,256,S4>>>(A, WL(9), B, ST(8),  ST(9), C, D);
    I5 <<<1024,256,S4>>>(B, WL(10),C, ST(9),  ST(10),nullptr, nullptr);
    // block 6
    I7 <<<1024,256,S4>>>(C, WL(11),B, ST(10), ST(11),D, A);
    I5 <<<1024,256,S4>>>(B, WL(12),D, ST(11), ST(12),nullptr, nullptr);
    // block 7 (32->64, stride 2)
    I8 <<< 256,256,S5>>>(D, WL(13),B, ST(12), ST(13),A, C);
    I9 <<< 256,256,S6>>>(B, WL(14),A, ST(13), ST(14),nullptr, nullptr);
    // block 8 (MODE3 pad shortcut, prev 32ch@16)
    I10<<< 256,256,S6>>>(A, WL(15),B, ST(14), ST(15),C, D);
    I9 <<< 256,256,S6>>>(B, WL(16),C, ST(15), ST(16),nullptr, nullptr);
    // block 9
    I11<<< 256,256,S6>>>(C, WL(17),B, ST(16), ST(17),D, A);
    I9 <<< 256,256,S6>>>(B, WL(18),D, ST(17), ST(18),nullptr, nullptr);
    // fused final residual + pool + fc
    poolfc_k<<<NB,64>>>(D, ST(18), A, Wfc, bfc, y);
}